// round 3
// baseline (speedup 1.0000x reference)
#include <cuda_runtime.h>

#define NN 100000
#define EE 3200000
#define RR 8
#define NB (NN * RR)                 // 800000 buckets (dst*8+rel)
#define SCAN_BLK 1024
#define SCAN_ITEMS 4
#define SCAN_CHUNK (SCAN_BLK * SCAN_ITEMS)              // 4096
#define SCAN_NBLK ((NB + SCAN_CHUNK - 1) / SCAN_CHUNK)  // 196
#define WPAD 260                     // padded W row stride (floats): conflict-free across 8 relations

// ---- device scratch (no allocation allowed) ----
__device__ __align__(16) int   g_cnt[NB];
__device__ __align__(16) int   g_off[NB + 1];
__device__ __align__(16) int   g_bsum[SCAN_NBLK];
__device__ __align__(16) int   g_boff[SCAN_NBLK];
__device__ __align__(16) int   g_pos[EE];
__device__ __align__(16) int   g_srt[EE];
__device__ __align__(16) float g_h[NN * 16];

__global__ void k_zero_cnt() {
    int i = blockIdx.x * blockDim.x + threadIdx.x;
    if (i < NB) g_cnt[i] = 0;
}

// One int atomic per edge: count + within-bucket position.
__global__ void k_hist(const int* __restrict__ dst, const int* __restrict__ et) {
    int e = blockIdx.x * blockDim.x + threadIdx.x;
    if (e >= EE) return;
    int key = dst[e] * RR + et[e];
    g_pos[e] = atomicAdd(&g_cnt[key], 1);
}

// ---- exclusive scan of g_cnt -> g_off ----
__global__ void k_scan_reduce() {
    __shared__ int sh[SCAN_BLK];
    int t = threadIdx.x, b = blockIdx.x;
    int i0 = b * SCAN_CHUNK + t * SCAN_ITEMS;
    int s = 0;
#pragma unroll
    for (int j = 0; j < SCAN_ITEMS; j++) {
        int i = i0 + j;
        s += (i < NB) ? g_cnt[i] : 0;
    }
    sh[t] = s;
    __syncthreads();
    for (int ofs = SCAN_BLK / 2; ofs > 0; ofs >>= 1) {
        if (t < ofs) sh[t] += sh[t + ofs];
        __syncthreads();
    }
    if (t == 0) g_bsum[b] = sh[0];
}

// single-block parallel scan of the 196 block sums (was serial 1-thread)
__global__ void k_scan_mid() {
    __shared__ int sh[256];
    int t = threadIdx.x;
    int v = (t < SCAN_NBLK) ? g_bsum[t] : 0;
    sh[t] = v;
    __syncthreads();
    for (int ofs = 1; ofs < 256; ofs <<= 1) {
        int a = (t >= ofs) ? sh[t - ofs] : 0;
        __syncthreads();
        sh[t] += a;
        __syncthreads();
    }
    if (t < SCAN_NBLK) g_boff[t] = sh[t] - v;   // exclusive
    if (t == 255) g_off[NB] = sh[255];          // == EE
}

__global__ void k_scan_write() {
    __shared__ int sh[SCAN_BLK];
    int t = threadIdx.x, b = blockIdx.x;
    int i0 = b * SCAN_CHUNK + t * SCAN_ITEMS;
    int v[SCAN_ITEMS];
    int tot = 0;
#pragma unroll
    for (int j = 0; j < SCAN_ITEMS; j++) {
        int i = i0 + j;
        v[j] = (i < NB) ? g_cnt[i] : 0;
        tot += v[j];
    }
    sh[t] = tot;
    __syncthreads();
    for (int ofs = 1; ofs < SCAN_BLK; ofs <<= 1) {
        int add = (t >= ofs) ? sh[t - ofs] : 0;
        __syncthreads();
        sh[t] += add;
        __syncthreads();
    }
    int base = g_boff[b] + sh[t] - tot;  // exclusive
#pragma unroll
    for (int j = 0; j < SCAN_ITEMS; j++) {
        int i = i0 + j;
        if (i < NB) g_off[i] = base;
        base += v[j];
    }
}

// Atomic-free scatter: place src of edge e into its bucket slot.
__global__ void k_scatter(const int* __restrict__ src, const int* __restrict__ dst,
                          const int* __restrict__ et) {
    int e = blockIdx.x * blockDim.x + threadIdx.x;
    if (e >= EE) return;
    int key = dst[e] * RR + et[e];
    g_srt[g_off[key] + g_pos[e]] = src[e];
}

// Gather RGCN layer: 8 threads per node, one per relation bucket.
// out_i = sum_r (1/n_r)*(sum_{j in N_r(i)} x_j) @ W_r + x_i @ root + b
// L==1: relu epilogue; L==2: log-softmax epilogue.
// 256 threads = 32 nodes/block; NN % 32 == 0 -> no ragged blocks, all lanes live.
template <int L>
__global__ void __launch_bounds__(256) k_agg(const float* __restrict__ xin,
                                             const float* __restrict__ W,
                                             const float* __restrict__ root,
                                             const float* __restrict__ bias,
                                             float* __restrict__ out) {
    __shared__ __align__(16) float sW[RR * WPAD];
    __shared__ __align__(16) float sR[256];
    __shared__ float sB[16];
    int t = threadIdx.x;
#pragma unroll
    for (int i = t; i < RR * 256; i += 256) {
        int r = i >> 8, k = i & 255;
        sW[r * WPAD + k] = __ldg(W + i);
    }
    sR[t] = __ldg(root + t);
    if (t < 16) sB[t] = __ldg(bias + t);
    __syncthreads();

    int node = blockIdx.x * 32 + (t >> 3);
    int r = t & 7;

    // --- bucket sum over this (node, r) group ---
    float sum[16];
#pragma unroll
    for (int c = 0; c < 16; c++) sum[c] = 0.0f;
    int b = node * RR + r;
    int o0 = __ldg(&g_off[b]);
    int o1 = __ldg(&g_off[b + 1]);
    for (int i = o0; i < o1; i++) {
        int s = __ldg(g_srt + i);
        const float4* p = (const float4*)(xin + (size_t)s * 16);
        float4 a0 = __ldg(p + 0), a1 = __ldg(p + 1), a2 = __ldg(p + 2), a3 = __ldg(p + 3);
        sum[0] += a0.x;  sum[1] += a0.y;  sum[2] += a0.z;  sum[3] += a0.w;
        sum[4] += a1.x;  sum[5] += a1.y;  sum[6] += a1.z;  sum[7] += a1.w;
        sum[8] += a2.x;  sum[9] += a2.y;  sum[10] += a2.z; sum[11] += a2.w;
        sum[12] += a3.x; sum[13] += a3.y; sum[14] += a3.z; sum[15] += a3.w;
    }

    // --- per-thread partial output ---
    float acc[16];
    if (r == 0) {
        // bias + self term x_node @ root on the r==0 lane of each group
        float xs[16];
        const float4* xr = (const float4*)(xin + (size_t)node * 16);
#pragma unroll
        for (int j = 0; j < 4; j++) {
            float4 v = __ldg(xr + j);
            xs[4 * j] = v.x; xs[4 * j + 1] = v.y; xs[4 * j + 2] = v.z; xs[4 * j + 3] = v.w;
        }
#pragma unroll
        for (int c = 0; c < 16; c++) acc[c] = sB[c];
#pragma unroll
        for (int k = 0; k < 16; k++) {
            float xv = xs[k];
#pragma unroll
            for (int c = 0; c < 16; c++) acc[c] = fmaf(xv, sR[k * 16 + c], acc[c]);
        }
    } else {
#pragma unroll
        for (int c = 0; c < 16; c++) acc[c] = 0.0f;
    }

    int n = o1 - o0;
    if (n > 0) {
        float inv = 1.0f / (float)n;
        const float4* Wr = (const float4*)(sW + r * WPAD);
#pragma unroll
        for (int k = 0; k < 16; k++) {
            float v = sum[k] * inv;
#pragma unroll
            for (int j = 0; j < 4; j++) {
                float4 w = Wr[k * 4 + j];
                acc[4 * j + 0] = fmaf(v, w.x, acc[4 * j + 0]);
                acc[4 * j + 1] = fmaf(v, w.y, acc[4 * j + 1]);
                acc[4 * j + 2] = fmaf(v, w.z, acc[4 * j + 2]);
                acc[4 * j + 3] = fmaf(v, w.w, acc[4 * j + 3]);
            }
        }
    }

    // --- reduce over the 8 relation lanes (butterfly; all lanes end with full row) ---
#pragma unroll
    for (int ofs = 4; ofs >= 1; ofs >>= 1) {
#pragma unroll
        for (int c = 0; c < 16; c++)
            acc[c] += __shfl_xor_sync(0xFFFFFFFFu, acc[c], ofs);
    }

    // --- epilogue ---
    if (L == 1) {
#pragma unroll
        for (int c = 0; c < 16; c++) acc[c] = fmaxf(acc[c], 0.0f);
    } else {
        float m = acc[0];
#pragma unroll
        for (int c = 1; c < 16; c++) m = fmaxf(m, acc[c]);
        float s = 0.0f;
#pragma unroll
        for (int c = 0; c < 16; c++) s += expf(acc[c] - m);
        float l = m + logf(s);
#pragma unroll
        for (int c = 0; c < 16; c++) acc[c] -= l;
    }

    // lanes r=0..3 write float4 #r -> contiguous 64B row
    if (r < 4) {
        ((float4*)(out + (size_t)node * 16))[r] =
            make_float4(acc[4 * r], acc[4 * r + 1], acc[4 * r + 2], acc[4 * r + 3]);
    }
}

extern "C" void kernel_launch(void* const* d_in, const int* in_sizes, int n_in,
                              void* d_out, int out_size) {
    const float* embed = (const float*)d_in[0];
    const float* W1    = (const float*)d_in[1];
    const float* root1 = (const float*)d_in[2];
    const float* b1    = (const float*)d_in[3];
    const float* W2    = (const float*)d_in[4];
    const float* root2 = (const float*)d_in[5];
    const float* b2    = (const float*)d_in[6];
    const int*   ei    = (const int*)d_in[7];   // [2, E]
    const int*   et    = (const int*)d_in[8];   // [E]
    const int* src = ei;
    const int* dst = ei + EE;
    float* out = (float*)d_out;
    (void)in_sizes; (void)n_in; (void)out_size;

    const int TB = 256;

    // build CSR by (dst, rel) — shared by both layers
    k_zero_cnt<<<(NB + TB - 1) / TB, TB>>>();
    k_hist<<<(EE + TB - 1) / TB, TB>>>(dst, et);
    k_scan_reduce<<<SCAN_NBLK, SCAN_BLK>>>();
    k_scan_mid<<<1, 256>>>();
    k_scan_write<<<SCAN_NBLK, SCAN_BLK>>>();
    k_scatter<<<(EE + TB - 1) / TB, TB>>>(src, dst, et);

    // layer 1 (relu fused), layer 2 (log-softmax fused); 8 threads/node
    k_agg<1><<<NN / 32, 256>>>(embed, W1, root1, b1, g_h);
    k_agg<2><<<NN / 32, 256>>>(g_h, W2, root2, b2, out);
}